// round 2
// baseline (speedup 1.0000x reference)
#include <cuda_runtime.h>
#include <math.h>

#define Bc 8
#define Sc 512
#define Nc (Sc*Sc)          // 262144 cells per batch
#define NB 128              // blocks per batch
#define TPB 256
#define CPB (Nc/NB)         // 2048 cells per block
#define ITERS 20
#define EPSF 1e-6f
#define INVH 511.0f
#define HF (1.0f/511.0f)
#define HH (HF*HF)
#define GAMMA_F 10.0f
#define THRESH_F 0.5f

// ---- scratch (static device globals; no runtime allocation) ----
__device__ float g_cxs[Bc*(Sc-1)*Sc];   // harmonic x-face coeff, pre-scaled by 1/h^2
__device__ float g_cys[Bc*Sc*(Sc-1)];   // harmonic y-face coeff, pre-scaled by 1/h^2
__device__ float g_lap[Bc*Nc];
__device__ float g_rho[Bc*Nc];          // interface indicator
__device__ float g_P[Bc*Nc];            // beta_n*nhx - beta_t*nhy
__device__ float g_Q[Bc*Nc];            // beta_n*nhy + beta_t*nhx
__device__ float g_BB[Bc*Nc];           // beta_bulk (deinterleaved)
__device__ float g_BNX[Bc*Nc];          // beta_b * bnx
__device__ float g_BNY[Bc*Nc];          // beta_b * bny
__device__ float g_RB[Nc];              // rho_bdry (position only)
__device__ float g_r[Bc*Nc];
__device__ float g_pp[2][Bc*Nc];        // ping-pong p
__device__ float g_xs[Bc*Nc];
__device__ float g_ap[Bc*Nc];
__device__ float g_pAp[Bc*NB];
__device__ float g_rr[2][Bc*NB];        // ping-pong r.r partials

__device__ __forceinline__ float blockReduce(float v, float* sh) {
    sh[threadIdx.x] = v;
    __syncthreads();
#pragma unroll
    for (int s = TPB >> 1; s > 0; s >>= 1) {
        if (threadIdx.x < s) sh[threadIdx.x] += sh[threadIdx.x + s];
        __syncthreads();
    }
    float r = sh[0];
    __syncthreads();
    return r;
}

__device__ __forceinline__ float reducePartials(const float* arr, float* sh) {
    float v = (threadIdx.x < NB) ? arr[threadIdx.x] : 0.f;
    return blockReduce(v, sh);
}

// =====================================================================
// S1: per-cell precompute (lap, interface fields, face coefficients)
// =====================================================================
__global__ void s1_kernel(const float* __restrict__ coeff,
                          const float* __restrict__ u,
                          const float* __restrict__ beta) {
    int b = blockIdx.y;
    size_t off = (size_t)b * Nc;
    const float* C = coeff + off;
    const float* U = u + off;
    const float4* B4 = (const float4*)beta + off;
    int base = blockIdx.x * CPB;

    for (int t = threadIdx.x; t < CPB; t += TPB) {
        int idx = base + t;
        int i = idx >> 9;
        int j = idx & (Sc - 1);
        float c = C[idx];

        if (i < Sc - 1) {
            float cn = C[idx + Sc];
            g_cxs[(size_t)b*(Sc-1)*Sc + idx] = (2.f*c*cn / (c + cn + EPSF)) * (INVH*INVH);
        }
        if (j < Sc - 1) {
            float ce = C[idx + 1];
            g_cys[(size_t)b*Sc*(Sc-1) + (size_t)i*(Sc-1) + j] = (2.f*c*ce / (c + ce + EPSF)) * (INVH*INVH);
        }

        float lap = 0.f;
        if (i > 0 && i < Sc-1 && j > 0 && j < Sc-1) {
            float uc = U[idx];
            lap = ((U[idx+Sc]-uc)*INVH - (uc-U[idx-Sc])*INVH)*INVH
                + ((U[idx+1 ]-uc)*INVH - (uc-U[idx-1 ])*INVH)*INVH;
        }
        g_lap[off + idx] = lap;

        // centered/one-sided gradient of log(max(coeff,eps))
        float lc = logf(fmaxf(c, EPSF));
        float glx, gly;
        if (i == 0)          glx = (logf(fmaxf(C[idx+Sc],EPSF)) - lc) * INVH;
        else if (i == Sc-1)  glx = (lc - logf(fmaxf(C[idx-Sc],EPSF))) * INVH;
        else                 glx = (logf(fmaxf(C[idx+Sc],EPSF)) - logf(fmaxf(C[idx-Sc],EPSF))) * (0.5f*INVH);
        if (j == 0)          gly = (logf(fmaxf(C[idx+1],EPSF)) - lc) * INVH;
        else if (j == Sc-1)  gly = (lc - logf(fmaxf(C[idx-1],EPSF))) * INVH;
        else                 gly = (logf(fmaxf(C[idx+1],EPSF)) - logf(fmaxf(C[idx-1],EPSF))) * (0.5f*INVH);

        float eta = sqrtf(glx*glx + gly*gly + EPSF);
        float rho = 1.f / (1.f + expf(-GAMMA_F * (eta - THRESH_F)));
        float nhx = glx / eta, nhy = gly / eta;

        float4 bv = B4[idx];
        g_rho[off+idx] = rho;
        g_P[off+idx]   = bv.y*nhx - bv.z*nhy;
        g_Q[off+idx]   = bv.y*nhy + bv.z*nhx;
        g_BB[off+idx]  = bv.x;

        // boundary geometry, double precision to match numpy argmin ties exactly
        double dl = 1.0 / 511.0;
        double xx = (i == Sc-1) ? 1.0 : (double)i * dl;
        double yy = (j == Sc-1) ? 1.0 : (double)j * dl;
        double a0 = xx, a1 = 1.0 - xx, a2 = yy, a3 = 1.0 - yy;
        double best = a0; int k = 0;
        if (a1 < best) { best = a1; k = 1; }
        if (a2 < best) { best = a2; k = 2; }
        if (a3 < best) { best = a3; k = 3; }
        float bnx = (k == 0) ? -1.f : ((k == 1) ? 1.f : 0.f);
        float bny = (k == 2) ? -1.f : ((k == 3) ? 1.f : 0.f);
        g_BNX[off+idx] = bv.w * bnx;
        g_BNY[off+idx] = bv.w * bny;
        if (b == 0) {
            float dd = (float)best;
            g_RB[idx] = expf(-(dd*dd) / (0.15f*0.15f));
        }
    }
}

// =====================================================================
// S2: rhs = div(tau), init r = p = rhs, x = 0, rr partials -> slot 0
// =====================================================================
__device__ __forceinline__ float fluxX(const float* C, const float* U, const float* LAP,
                                       const float* RHO, const float* PP, const float* BB,
                                       const float* BNX, int a) {
    int b2 = a + Sc;
    float ca = C[a], cb = C[b2];
    float cxf = 2.f*ca*cb / (ca + cb + EPSF);
    float gux = (U[b2] - U[a]) * INVH;
    float lgx = (LAP[b2] - LAP[a]) * INVH;
    return 0.5f*(BB[a]+BB[b2]) * HH * cxf * lgx
         + 0.5f*(RHO[a]+RHO[b2]) * (0.5f*(PP[a]+PP[b2])) * cxf * gux
         + 0.5f*(g_RB[a]+g_RB[b2]) * (0.5f*(BNX[a]+BNX[b2])) * cxf * gux;
}

__device__ __forceinline__ float fluxY(const float* C, const float* U, const float* LAP,
                                       const float* RHO, const float* QQ, const float* BB,
                                       const float* BNY, int a) {
    int b2 = a + 1;
    float ca = C[a], cb = C[b2];
    float cyf = 2.f*ca*cb / (ca + cb + EPSF);
    float guy = (U[b2] - U[a]) * INVH;
    float lgy = (LAP[b2] - LAP[a]) * INVH;
    return 0.5f*(BB[a]+BB[b2]) * HH * cyf * lgy
         + 0.5f*(RHO[a]+RHO[b2]) * (0.5f*(QQ[a]+QQ[b2])) * cyf * guy
         + 0.5f*(g_RB[a]+g_RB[b2]) * (0.5f*(BNY[a]+BNY[b2])) * cyf * guy;
}

__global__ void s2_kernel(const float* __restrict__ coeff, const float* __restrict__ u) {
    __shared__ float sh[TPB];
    int b = blockIdx.y;
    size_t off = (size_t)b * Nc;
    const float* C = coeff + off;
    const float* U = u + off;
    const float* LAP = g_lap + off;
    const float* RHO = g_rho + off;
    const float* PP  = g_P + off;
    const float* QQ  = g_Q + off;
    const float* BB  = g_BB + off;
    const float* BNX = g_BNX + off;
    const float* BNY = g_BNY + off;
    int base = blockIdx.x * CPB;
    float acc = 0.f;

    for (int t = threadIdx.x; t < CPB; t += TPB) {
        int idx = base + t;
        int i = idx >> 9;
        int j = idx & (Sc - 1);
        float rhs = 0.f;
        if (i > 0 && i < Sc-1 && j > 0 && j < Sc-1) {
            float fxN = fluxX(C, U, LAP, RHO, PP, BB, BNX, idx);
            float fxS = fluxX(C, U, LAP, RHO, PP, BB, BNX, idx - Sc);
            float fyE = fluxY(C, U, LAP, RHO, QQ, BB, BNY, idx);
            float fyW = fluxY(C, U, LAP, RHO, QQ, BB, BNY, idx - 1);
            rhs = (fxN - fxS) * INVH + (fyE - fyW) * INVH;
        }
        g_r[off+idx] = rhs;
        g_pp[0][off+idx] = rhs;
        g_xs[off+idx] = 0.f;
        acc += rhs * rhs;
    }
    float tot = blockReduce(acc, sh);
    if (threadIdx.x == 0) g_rr[0][b*NB + blockIdx.x] = tot;
}

// =====================================================================
// K1 (iter 0 only): ap = A(p), p.Ap partials
// =====================================================================
__global__ void k1_kernel() {
    __shared__ float sh[TPB];
    int b = blockIdx.y;
    size_t off = (size_t)b * Nc;
    const float* P  = g_pp[0] + off;
    const float* CX = g_cxs + (size_t)b*(Sc-1)*Sc;
    const float* CY = g_cys + (size_t)b*Sc*(Sc-1);
    int base = blockIdx.x * CPB;
    float acc = 0.f;

    for (int t = threadIdx.x; t < CPB; t += TPB) {
        int idx = base + t;
        int i = idx >> 9;
        int j = idx & (Sc - 1);
        float ap = 0.f;
        if (i > 0 && i < Sc-1 && j > 0 && j < Sc-1) {
            float pc = P[idx];
            ap = CX[idx]*(pc - P[idx+Sc]) + CX[idx-Sc]*(pc - P[idx-Sc])
               + CY[(size_t)i*(Sc-1)+j]*(pc - P[idx+1]) + CY[(size_t)i*(Sc-1)+j-1]*(pc - P[idx-1]);
            acc += pc * ap;
        }
        g_ap[off+idx] = ap;
    }
    float tot = blockReduce(acc, sh);
    if (threadIdx.x == 0) g_pAp[b*NB + blockIdx.x] = tot;
}

// =====================================================================
// K31 (iters 1..19): p_new = r + beta*p_old (on the fly for neighbors),
// ap = A(p_new), p.Ap partials. Ping-pong p.
// =====================================================================
__global__ void k31_kernel(int pPrev, int pCur, int sCur, int sPrev) {
    __shared__ float sh[TPB];
    int b = blockIdx.y;
    float rnI = reducePartials(g_rr[sCur]  + b*NB, sh);
    float rnP = reducePartials(g_rr[sPrev] + b*NB, sh);
    float beta = rnI / fmaxf(rnP, EPSF);

    size_t off = (size_t)b * Nc;
    const float* R  = g_r + off;
    const float* PO = g_pp[pPrev] + off;
    float* PN = g_pp[pCur] + off;
    const float* CX = g_cxs + (size_t)b*(Sc-1)*Sc;
    const float* CY = g_cys + (size_t)b*Sc*(Sc-1);
    int base = blockIdx.x * CPB;
    float acc = 0.f;

    for (int t = threadIdx.x; t < CPB; t += TPB) {
        int idx = base + t;
        int i = idx >> 9;
        int j = idx & (Sc - 1);
        float pc = R[idx] + beta * PO[idx];
        float ap = 0.f;
        if (i > 0 && i < Sc-1 && j > 0 && j < Sc-1) {
            float pu = R[idx+Sc] + beta * PO[idx+Sc];
            float pd = R[idx-Sc] + beta * PO[idx-Sc];
            float pe = R[idx+1]  + beta * PO[idx+1];
            float pw = R[idx-1]  + beta * PO[idx-1];
            ap = CX[idx]*(pc - pu) + CX[idx-Sc]*(pc - pd)
               + CY[(size_t)i*(Sc-1)+j]*(pc - pe) + CY[(size_t)i*(Sc-1)+j-1]*(pc - pw);
            acc += pc * ap;
        }
        PN[idx] = pc;
        g_ap[off+idx] = ap;
    }
    float tot = blockReduce(acc, sh);
    if (threadIdx.x == 0) g_pAp[b*NB + blockIdx.x] = tot;
}

// =====================================================================
// K2: alpha = rn/max(pAp,eps); x += alpha p; r -= alpha ap; rr partials
// =====================================================================
__global__ void k2_kernel(int pCur, int sCur, int sNext) {
    __shared__ float sh[TPB];
    int b = blockIdx.y;
    float pap = reducePartials(g_pAp + b*NB, sh);
    float rn  = reducePartials(g_rr[sCur] + b*NB, sh);
    float alpha = rn / fmaxf(pap, EPSF);

    size_t off = (size_t)b * Nc;
    float* X = g_xs + off;
    float* R = g_r + off;
    const float* P  = g_pp[pCur] + off;
    const float* AP = g_ap + off;
    int base = blockIdx.x * CPB;
    float acc = 0.f;

    for (int t = threadIdx.x; t < CPB; t += TPB) {
        int idx = base + t;
        X[idx] += alpha * P[idx];
        float rv = R[idx] - alpha * AP[idx];
        R[idx] = rv;
        acc += rv * rv;
    }
    float tot = blockReduce(acc, sh);
    if (threadIdx.x == 0) g_rr[sNext][b*NB + blockIdx.x] = tot;
}

// =====================================================================
// K4: out = zb(u + x)
// =====================================================================
__global__ void k4_kernel(const float* __restrict__ u, float* __restrict__ out) {
    int b = blockIdx.y;
    size_t off = (size_t)b * Nc;
    int base = blockIdx.x * CPB;
    for (int t = threadIdx.x; t < CPB; t += TPB) {
        int idx = base + t;
        int i = idx >> 9;
        int j = idx & (Sc - 1);
        float v = 0.f;
        if (i > 0 && i < Sc-1 && j > 0 && j < Sc-1)
            v = u[off+idx] + g_xs[off+idx];
        out[off+idx] = v;
    }
}

extern "C" void kernel_launch(void* const* d_in, const int* in_sizes, int n_in,
                              void* d_out, int out_size) {
    const float* coeff = (const float*)d_in[0];
    const float* u     = (const float*)d_in[1];
    const float* beta  = (const float*)d_in[2];
    float* out = (float*)d_out;

    dim3 grid(NB, Bc), blk(TPB);
    s1_kernel<<<grid, blk>>>(coeff, u, beta);
    s2_kernel<<<grid, blk>>>(coeff, u);

    // iteration 0
    k1_kernel<<<grid, blk>>>();
    k2_kernel<<<grid, blk>>>(0, 0, 1);

    for (int i = 1; i < ITERS; i++) {
        int pPrev = (i - 1) & 1;
        int pCur  = i & 1;
        int sCur  = i & 1;        // rn_i partials slot
        int sPrev = (i - 1) & 1;  // rn_{i-1} partials slot
        k31_kernel<<<grid, blk>>>(pPrev, pCur, sCur, sPrev);
        k2_kernel<<<grid, blk>>>(pCur, sCur, (i + 1) & 1);
    }

    k4_kernel<<<grid, blk>>>(u, out);
}

// round 4
// speedup vs baseline: 1.5806x; 1.5806x over previous
#include <cuda_runtime.h>
#include <math.h>

#define Bc 8
#define Sc 512
#define Nc (Sc*Sc)          // 262144 cells per batch
#define NBs 128             // blocks per batch for setup kernels
#define TPBs 256
#define CPBs (Nc/NBs)       // 2048 cells per block (setup)
#define ITERS 20
#define EPSF 1e-6f
#define INVH 511.0f
#define HF (1.0f/511.0f)
#define HH (HF*HF)
#define GAMMA_F 10.0f
#define THRESH_F 0.5f

// persistent kernel config
#define PB 256              // total persistent blocks (<= 148*2 capacity)
#define PT 512              // threads per block
#define BPB 32              // blocks per batch
#define ROWS 16             // rows per block (32*16 = 512)

// ---- scratch (static device globals) ----
__device__ float g_cxs[Bc*(Sc-1)*Sc];   // harmonic x-face coeff * 1/h^2
__device__ float g_cys[Bc*Sc*(Sc-1)];   // harmonic y-face coeff * 1/h^2
__device__ float g_lap[Bc*Nc];
__device__ float g_rho[Bc*Nc];
__device__ float g_P[Bc*Nc];
__device__ float g_Q[Bc*Nc];
__device__ float g_BB[Bc*Nc];
__device__ float g_BNX[Bc*Nc];
__device__ float g_BNY[Bc*Nc];
__device__ float g_RB[Nc];
__device__ float g_r[Bc*Nc];            // rhs from s2
__device__ float g_p[Bc*Nc];            // only edge rows used
__device__ float g_pap[Bc*BPB];
__device__ float g_rrp[Bc*BPB];
__device__ unsigned g_cnt[Bc];          // barrier counters

// =====================================================================
// S1: per-cell precompute (lap, interface fields, face coefficients)
// =====================================================================
__global__ void s1_kernel(const float* __restrict__ coeff,
                          const float* __restrict__ u,
                          const float* __restrict__ beta) {
    int b = blockIdx.y;
    size_t off = (size_t)b * Nc;
    const float* C = coeff + off;
    const float* U = u + off;
    const float4* B4 = (const float4*)beta + off;
    int base = blockIdx.x * CPBs;

    for (int t = threadIdx.x; t < CPBs; t += TPBs) {
        int idx = base + t;
        int i = idx >> 9;
        int j = idx & (Sc - 1);
        float c = C[idx];

        if (i < Sc - 1) {
            float cn = C[idx + Sc];
            g_cxs[(size_t)b*(Sc-1)*Sc + idx] = (2.f*c*cn / (c + cn + EPSF)) * (INVH*INVH);
        }
        if (j < Sc - 1) {
            float ce = C[idx + 1];
            g_cys[(size_t)b*Sc*(Sc-1) + (size_t)i*(Sc-1) + j] = (2.f*c*ce / (c + ce + EPSF)) * (INVH*INVH);
        }

        float lap = 0.f;
        if (i > 0 && i < Sc-1 && j > 0 && j < Sc-1) {
            float uc = U[idx];
            lap = ((U[idx+Sc]-uc)*INVH - (uc-U[idx-Sc])*INVH)*INVH
                + ((U[idx+1 ]-uc)*INVH - (uc-U[idx-1 ])*INVH)*INVH;
        }
        g_lap[off + idx] = lap;

        float lc = logf(fmaxf(c, EPSF));
        float glx, gly;
        if (i == 0)          glx = (logf(fmaxf(C[idx+Sc],EPSF)) - lc) * INVH;
        else if (i == Sc-1)  glx = (lc - logf(fmaxf(C[idx-Sc],EPSF))) * INVH;
        else                 glx = (logf(fmaxf(C[idx+Sc],EPSF)) - logf(fmaxf(C[idx-Sc],EPSF))) * (0.5f*INVH);
        if (j == 0)          gly = (logf(fmaxf(C[idx+1],EPSF)) - lc) * INVH;
        else if (j == Sc-1)  gly = (lc - logf(fmaxf(C[idx-1],EPSF))) * INVH;
        else                 gly = (logf(fmaxf(C[idx+1],EPSF)) - logf(fmaxf(C[idx-1],EPSF))) * (0.5f*INVH);

        float eta = sqrtf(glx*glx + gly*gly + EPSF);
        float rho = 1.f / (1.f + expf(-GAMMA_F * (eta - THRESH_F)));
        float nhx = glx / eta, nhy = gly / eta;

        float4 bv = B4[idx];
        g_rho[off+idx] = rho;
        g_P[off+idx]   = bv.y*nhx - bv.z*nhy;
        g_Q[off+idx]   = bv.y*nhy + bv.z*nhx;
        g_BB[off+idx]  = bv.x;

        // boundary geometry in double to match numpy argmin ties
        double dl = 1.0 / 511.0;
        double xx = (i == Sc-1) ? 1.0 : (double)i * dl;
        double yy = (j == Sc-1) ? 1.0 : (double)j * dl;
        double a0 = xx, a1 = 1.0 - xx, a2 = yy, a3 = 1.0 - yy;
        double best = a0; int k = 0;
        if (a1 < best) { best = a1; k = 1; }
        if (a2 < best) { best = a2; k = 2; }
        if (a3 < best) { best = a3; k = 3; }
        float bnx = (k == 0) ? -1.f : ((k == 1) ? 1.f : 0.f);
        float bny = (k == 2) ? -1.f : ((k == 3) ? 1.f : 0.f);
        g_BNX[off+idx] = bv.w * bnx;
        g_BNY[off+idx] = bv.w * bny;
        if (b == 0) {
            float dd = (float)best;
            g_RB[idx] = expf(-(dd*dd) / (0.15f*0.15f));
        }
    }
}

// =====================================================================
// S2: rhs = div(tau) -> g_r
// =====================================================================
__device__ __forceinline__ float fluxX(const float* C, const float* U, const float* LAP,
                                       const float* RHO, const float* PP, const float* BB,
                                       const float* BNX, int a) {
    int b2 = a + Sc;
    float ca = C[a], cb = C[b2];
    float cxf = 2.f*ca*cb / (ca + cb + EPSF);
    float gux = (U[b2] - U[a]) * INVH;
    float lgx = (LAP[b2] - LAP[a]) * INVH;
    return 0.5f*(BB[a]+BB[b2]) * HH * cxf * lgx
         + 0.5f*(RHO[a]+RHO[b2]) * (0.5f*(PP[a]+PP[b2])) * cxf * gux
         + 0.5f*(g_RB[a]+g_RB[b2]) * (0.5f*(BNX[a]+BNX[b2])) * cxf * gux;
}

__device__ __forceinline__ float fluxY(const float* C, const float* U, const float* LAP,
                                       const float* RHO, const float* QQ, const float* BB,
                                       const float* BNY, int a) {
    int b2 = a + 1;
    float ca = C[a], cb = C[b2];
    float cyf = 2.f*ca*cb / (ca + cb + EPSF);
    float guy = (U[b2] - U[a]) * INVH;
    float lgy = (LAP[b2] - LAP[a]) * INVH;
    return 0.5f*(BB[a]+BB[b2]) * HH * cyf * lgy
         + 0.5f*(RHO[a]+RHO[b2]) * (0.5f*(QQ[a]+QQ[b2])) * cyf * guy
         + 0.5f*(g_RB[a]+g_RB[b2]) * (0.5f*(BNY[a]+BNY[b2])) * cyf * guy;
}

__global__ void s2_kernel(const float* __restrict__ coeff, const float* __restrict__ u) {
    int b = blockIdx.y;
    size_t off = (size_t)b * Nc;
    const float* C = coeff + off;
    const float* U = u + off;
    const float* LAP = g_lap + off;
    const float* RHO = g_rho + off;
    const float* PP  = g_P + off;
    const float* QQ  = g_Q + off;
    const float* BB  = g_BB + off;
    const float* BNX = g_BNX + off;
    const float* BNY = g_BNY + off;
    int base = blockIdx.x * CPBs;

    for (int t = threadIdx.x; t < CPBs; t += TPBs) {
        int idx = base + t;
        int i = idx >> 9;
        int j = idx & (Sc - 1);
        float rhs = 0.f;
        if (i > 0 && i < Sc-1 && j > 0 && j < Sc-1) {
            float fxN = fluxX(C, U, LAP, RHO, PP, BB, BNX, idx);
            float fxS = fluxX(C, U, LAP, RHO, PP, BB, BNX, idx - Sc);
            float fyE = fluxY(C, U, LAP, RHO, QQ, BB, BNY, idx);
            float fyW = fluxY(C, U, LAP, RHO, QQ, BB, BNY, idx - 1);
            rhs = (fxN - fxS) * INVH + (fyE - fyW) * INVH;
        }
        g_r[off+idx] = rhs;
    }
}

// =====================================================================
// zero barrier counters (each launch/replay)
// =====================================================================
__global__ void zc_kernel() {
    if (threadIdx.x < Bc) g_cnt[threadIdx.x] = 0u;
}

// =====================================================================
// Persistent CG kernel
// =====================================================================
__device__ __forceinline__ void batch_barrier(unsigned* cnt, unsigned target) {
    __syncthreads();
    if (threadIdx.x == 0) {
        asm volatile("red.release.gpu.add.u32 [%0], %1;" :: "l"(cnt), "r"(1u) : "memory");
        unsigned v;
        do {
            asm volatile("ld.acquire.gpu.u32 %0, [%1];" : "=r"(v) : "l"(cnt) : "memory");
        } while (v < target);
    }
    __syncthreads();
}

// 512-thread deterministic sum; tid0 stores to gout. Caller must have a sync
// (batch_barrier entry) before sRed is reused.
__device__ __forceinline__ void blockSumStore(float v, float* sRed, float* gout) {
#pragma unroll
    for (int o = 16; o > 0; o >>= 1) v += __shfl_down_sync(0xffffffffu, v, o);
    if ((threadIdx.x & 31) == 0) sRed[threadIdx.x >> 5] = v;
    __syncthreads();
    if (threadIdx.x == 0) {
        float s = 0.f;
#pragma unroll
        for (int w = 0; w < 16; w++) s += sRed[w];
        *gout = s;
    }
}

// deterministic reduction of 32 partials, identical order in every block
__device__ __forceinline__ float reduce32(const float* g, float* sRed) {
    if (threadIdx.x < 32) {
        float v = g[threadIdx.x];
#pragma unroll
        for (int o = 16; o > 0; o >>= 1) v += __shfl_down_sync(0xffffffffu, v, o);
        if (threadIdx.x == 0) sRed[31] = v;
    }
    __syncthreads();
    float r = sRed[31];
    __syncthreads();
    return r;
}

#define SMEM_FLOATS (18*PT + 16*PT + 16*PT + 32)
#define SMEM_BYTES (SMEM_FLOATS * 4)

__global__ void __launch_bounds__(PT, 2)
cg_kernel(const float* __restrict__ u, float* __restrict__ out) {
    extern __shared__ float sm[];
    float* sP   = sm;                 // rows 0..17 (1..16 own, 0/17 halo)
    float* sR   = sm + 18*PT;         // 16 rows
    float* sAP  = sR + 16*PT;         // 16 rows
    float* sRed = sAP + 16*PT;        // 32 floats scratch

    const int t = threadIdx.x;
    const int blk = blockIdx.x;
    const int b = blk >> 5;
    const int rblk = blk & 31;
    const int R0 = rblk * ROWS;
    const size_t off = (size_t)b * Nc;
    const size_t gb = off + (size_t)R0 * Sc + t;
    const float* __restrict__ CX = g_cxs + (size_t)b*(Sc-1)*Sc;
    const float* __restrict__ CY = g_cys + (size_t)b*Sc*(Sc-1);
    unsigned* cnt = &g_cnt[b];
    unsigned tgt = 0;

    float x[ROWS], pc[ROWS];

    // ---- init: r from s2, p = r, x = 0, rr partials ----
    float acc = 0.f;
#pragma unroll
    for (int k = 0; k < ROWS; k++) {
        float rv = g_r[gb + k*Sc];
        sR[k*PT + t] = rv;
        sP[(k+1)*PT + t] = rv;
        pc[k] = rv;
        x[k] = 0.f;
        acc += rv * rv;
        if (k == 0 || k == ROWS-1) g_p[gb + k*Sc] = rv;
    }
    blockSumStore(acc, sRed, &g_rrp[b*BPB + rblk]);
    tgt += BPB; batch_barrier(cnt, tgt);
    float rr = reduce32(g_rrp + b*BPB, sRed);
    float rr_old = rr;

    for (int it = 0; it < ITERS; it++) {
        if (it > 0) {
            // ---- phase 1: p = r + beta*p ----
            float beta = rr / fmaxf(rr_old, EPSF);
#pragma unroll
            for (int k = 0; k < ROWS; k++) {
                float pv = sR[k*PT + t] + beta * pc[k];
                pc[k] = pv;
                sP[(k+1)*PT + t] = pv;
                if (k == 0 || k == ROWS-1) g_p[gb + k*Sc] = pv;
            }
            tgt += BPB; batch_barrier(cnt, tgt);
        }
        // ---- phase 2: halo load + ap = A(p), pAp partial ----
        sP[t]         = (rblk > 0)     ? g_p[gb - Sc]       : 0.f;
        sP[17*PT + t] = (rblk < BPB-1) ? g_p[gb + ROWS*Sc]  : 0.f;
        __syncthreads();

        float pAcc = 0.f;
#pragma unroll
        for (int k = 0; k < ROWS; k++) {
            int i = R0 + k;
            float ap = 0.f;
            if (i > 0 && i < Sc-1 && t > 0 && t < Sc-1) {
                float pcc = pc[k];
                float pu = sP[(k+2)*PT + t];
                float pd = sP[k*PT + t];
                float pe = sP[(k+1)*PT + t + 1];
                float pw = sP[(k+1)*PT + t - 1];
                float cxn = CX[(size_t)i*Sc + t];
                float cxs = CX[(size_t)(i-1)*Sc + t];
                float cye = CY[(size_t)i*(Sc-1) + t];
                float cyw = CY[(size_t)i*(Sc-1) + t - 1];
                ap = cxn*(pcc-pu) + cxs*(pcc-pd) + cye*(pcc-pe) + cyw*(pcc-pw);
                pAcc += pcc * ap;
            }
            sAP[k*PT + t] = ap;
        }
        blockSumStore(pAcc, sRed, &g_pap[b*BPB + rblk]);
        tgt += BPB; batch_barrier(cnt, tgt);
        float pap = reduce32(g_pap + b*BPB, sRed);
        float alpha = rr / fmaxf(pap, EPSF);

        // ---- phase 3: x += alpha p; r -= alpha ap; rr partial ----
        float racc = 0.f;
#pragma unroll
        for (int k = 0; k < ROWS; k++) {
            x[k] += alpha * pc[k];
            float rv = sR[k*PT + t] - alpha * sAP[k*PT + t];
            sR[k*PT + t] = rv;
            racc += rv * rv;
        }
        if (it < ITERS-1) {
            blockSumStore(racc, sRed, &g_rrp[b*BPB + rblk]);
            tgt += BPB; batch_barrier(cnt, tgt);
            rr_old = rr;
            rr = reduce32(g_rrp + b*BPB, sRed);
        }
    }

    // ---- output: out = zb(u + x) ----
#pragma unroll
    for (int k = 0; k < ROWS; k++) {
        int i = R0 + k;
        size_t gi = gb + k*Sc;
        float v = 0.f;
        if (i > 0 && i < Sc-1 && t > 0 && t < Sc-1) v = u[gi] + x[k];
        out[gi] = v;
    }
}

extern "C" void kernel_launch(void* const* d_in, const int* in_sizes, int n_in,
                              void* d_out, int out_size) {
    const float* coeff = (const float*)d_in[0];
    const float* u     = (const float*)d_in[1];
    const float* beta  = (const float*)d_in[2];
    float* out = (float*)d_out;

    cudaFuncSetAttribute(cg_kernel, cudaFuncAttributeMaxDynamicSharedMemorySize, SMEM_BYTES);

    zc_kernel<<<1, 32>>>();
    dim3 grid(NBs, Bc), blkd(TPBs);
    s1_kernel<<<grid, blkd>>>(coeff, u, beta);
    s2_kernel<<<grid, blkd>>>(coeff, u);
    cg_kernel<<<PB, PT, SMEM_BYTES>>>(u, out);
}